// round 1
// baseline (speedup 1.0000x reference)
#include <cuda_runtime.h>
#include <math.h>

#define EPS 1e-8f
#define RAD2DEG 57.295779513082320876798154814105f

// Inputs: data [N,64] f32, lab [N,3] f32, W [64,3] f32, b [3] f32
// Output: [N] f32

__global__ __launch_bounds__(256) void cosine_loss_kernel(
    const float* __restrict__ data,
    const float* __restrict__ lab,
    const float* __restrict__ W,
    const float* __restrict__ b,
    float* __restrict__ out,
    int N)
{
    // Stage W (transposed to [3][64]) + b into shared memory once per block.
    __shared__ __align__(16) float sW[3][64];
    __shared__ float sb[3];

    int t = threadIdx.x;
    if (t < 192) {
        int k = t / 3;       // input dim
        int c = t % 3;       // output channel
        sW[c][k] = W[t];     // W is [64,3] row-major: W[k*3+c]
    }
    if (t >= 192 && t < 195) {
        sb[t - 192] = b[t - 192];
    }
    __syncthreads();

    int row = blockIdx.x * blockDim.x + t;
    if (row >= N) return;

    const float4* __restrict__ dv =
        reinterpret_cast<const float4*>(data) + (size_t)row * 16;
    const float4* __restrict__ w0v = reinterpret_cast<const float4*>(sW[0]);
    const float4* __restrict__ w1v = reinterpret_cast<const float4*>(sW[1]);
    const float4* __restrict__ w2v = reinterpret_cast<const float4*>(sW[2]);

    float acc0 = 0.f, acc1 = 0.f, acc2 = 0.f;

    // Two halves of 8 chunks (= one 128B cache line per half), loads batched
    // back-to-back so sectors are consumed right after fetch.
    #pragma unroll
    for (int h = 0; h < 2; ++h) {
        float4 d[8];
        #pragma unroll
        for (int j = 0; j < 8; ++j) {
            d[j] = __ldcs(&dv[h * 8 + j]);
        }
        #pragma unroll
        for (int j = 0; j < 8; ++j) {
            int k = h * 8 + j;
            float4 w0 = w0v[k];
            float4 w1 = w1v[k];
            float4 w2 = w2v[k];
            acc0 += d[j].x * w0.x + d[j].y * w0.y + d[j].z * w0.z + d[j].w * w0.w;
            acc1 += d[j].x * w1.x + d[j].y * w1.y + d[j].z * w1.z + d[j].w * w1.w;
            acc2 += d[j].x * w2.x + d[j].y * w2.y + d[j].z * w2.z + d[j].w * w2.w;
        }
    }

    // pred = data @ W + b
    float p0 = acc0 + sb[0];
    float p1 = acc1 + sb[1];
    float p2 = acc2 + sb[2];

    // F.normalize(pred, dim=1)
    float n = sqrtf(p0 * p0 + p1 * p1 + p2 * p2);
    float inv = 1.0f / fmaxf(n, EPS);
    float pn0 = p0 * inv, pn1 = p1 * inv, pn2 = p2 * inv;

    // lab row
    const float* lr = lab + (size_t)row * 3;
    float l0 = __ldcs(&lr[0]);
    float l1 = __ldcs(&lr[1]);
    float l2 = __ldcs(&lr[2]);

    // cosine_similarity(pred_n, lab)
    float dot = pn0 * l0 + pn1 * l1 + pn2 * l2;
    float na = fmaxf(sqrtf(pn0 * pn0 + pn1 * pn1 + pn2 * pn2), EPS);
    float nb = fmaxf(sqrtf(l0 * l0 + l1 * l1 + l2 * l2), EPS);
    float cosv = dot / (na * nb);

    // acos in degrees, NaN -> 0
    float loss = acosf(cosv) * RAD2DEG;
    if (isnan(loss)) loss = 0.0f;

    out[row] = loss;
}

extern "C" void kernel_launch(void* const* d_in, const int* in_sizes, int n_in,
                              void* d_out, int out_size)
{
    const float* data = (const float*)d_in[0];
    const float* lab  = (const float*)d_in[1];
    const float* W    = (const float*)d_in[2];
    const float* b    = (const float*)d_in[3];
    float* out = (float*)d_out;

    int N = in_sizes[0] / 64;
    int threads = 256;
    int blocks = (N + threads - 1) / threads;
    cosine_loss_kernel<<<blocks, threads>>>(data, lab, W, b, out, N);
}